// round 8
// baseline (speedup 1.0000x reference)
#include <cuda_runtime.h>
#include <math.h>
#include <stdint.h>

#define NN 8192
#define KF 512
#define NH 256
#define FALPHA 0.5f

#define KCH 64
#define ROWB 272              // bytes per smem row: 64 floats + 16B pad (LDSM conflict-free)
#define OPBYTES (128 * ROWB)  // 34816 per operand per stage
#define STAGEB (2 * OPBYTES)  // 69632
#define SM_BYTES (2 * STAGEB) // 139264, DEPTH=2

// ---------------- device scratch ----------------
__device__ float g_rowsum[NN];
__device__ float g_colsum[NN];
__device__ float g_drow[NN];
__device__ float g_dcol[NN];
__device__ float g_adjr[(size_t)NN * NN]; // adj rounded to tf32
__device__ float g_xr  [NN * KF];         // x rounded to tf32
__device__ float g_W1T [NH * KF];         // W1^T rounded to tf32
__device__ float g_PT  [NH * NN];         // (x@W1)^T  exact
__device__ float g_PsT [NH * NN];         // (dcol ⊙ P)^T rounded tf32
__device__ float g_Y1T [NH * NN];         // (DAD@P)^T exact
__device__ float g_Y1sT[NH * NN];         // (dcol ⊙ Y1)^T rounded tf32
__device__ float g_HT  [NH * NN];         // H^T exact
__device__ float g_Q [NN * 2];
__device__ float g_Qs[NN * 2];
__device__ float g_Z1[NN * 2];
__device__ float g_Z1s[NN * 2];

// ---------------- helpers ----------------
__device__ __forceinline__ uint32_t smem_u32(const void* p) {
    uint32_t a;
    asm("{ .reg .u64 t; cvta.to.shared.u64 t, %1; cvt.u32.u64 %0, t; }" : "=r"(a) : "l"(p));
    return a;
}
__device__ __forceinline__ uint32_t f2tf(float f) {
    uint32_t r;
    asm("cvt.rna.tf32.f32 %0, %1;" : "=r"(r) : "f"(f));
    return r;
}
__device__ __forceinline__ float rtf(float f) { return __uint_as_float(f2tf(f)); }

__device__ __forceinline__ void mma_tf32(float* d, const uint32_t* a, const uint32_t* b) {
    asm volatile(
        "mma.sync.aligned.m16n8k8.row.col.f32.tf32.tf32.f32 "
        "{%0,%1,%2,%3}, {%4,%5,%6,%7}, {%8,%9}, {%0,%1,%2,%3};"
        : "+f"(d[0]), "+f"(d[1]), "+f"(d[2]), "+f"(d[3])
        : "r"(a[0]), "r"(a[1]), "r"(a[2]), "r"(a[3]), "r"(b[0]), "r"(b[1]));
}
#define LDSM4(r, addr) \
    asm volatile("ldmatrix.sync.aligned.m8n8.x4.shared.b16 {%0,%1,%2,%3}, [%4];" \
        : "=r"((r)[0]), "=r"((r)[1]), "=r"((r)[2]), "=r"((r)[3]) : "r"(addr))
#define CP16(dst, src) \
    asm volatile("cp.async.cg.shared.global [%0], [%1], 16;" :: "r"(dst), "l"(src) : "memory")
#define CP_COMMIT() asm volatile("cp.async.commit_group;" ::: "memory")

// ---------------- small kernels ----------------
__global__ void k_zero() {
    int i = blockIdx.x * 256 + threadIdx.x;
    if (i < NN) { g_rowsum[i] = 0.f; g_colsum[i] = 0.f; }
}

// fused: row/col sums over exact adj + write tf32-rounded copy
__global__ __launch_bounds__(256) void k_sums(const float* __restrict__ adj) {
    const int t    = threadIdx.x;
    const int c0   = blockIdx.x * 1024 + t * 4;
    const int r0   = blockIdx.y * 256;
    const int lane = t & 31;
    float4 cacc = make_float4(0.f, 0.f, 0.f, 0.f);
    for (int r = 0; r < 256; r++) {
        size_t base = (size_t)(r0 + r) * NN + c0;
        float4 v = *reinterpret_cast<const float4*>(adj + base);
        cacc.x += v.x; cacc.y += v.y; cacc.z += v.z; cacc.w += v.w;
        float rs = (v.x + v.y) + (v.z + v.w);
        #pragma unroll
        for (int o = 16; o; o >>= 1) rs += __shfl_down_sync(0xffffffffu, rs, o);
        if (lane == 0) atomicAdd(&g_rowsum[r0 + r], rs);
        float4 w = make_float4(rtf(v.x), rtf(v.y), rtf(v.z), rtf(v.w));
        *reinterpret_cast<float4*>(g_adjr + base) = w;
    }
    atomicAdd(&g_colsum[c0 + 0], cacc.x);
    atomicAdd(&g_colsum[c0 + 1], cacc.y);
    atomicAdd(&g_colsum[c0 + 2], cacc.z);
    atomicAdd(&g_colsum[c0 + 3], cacc.w);
}

__global__ void k_deg() {
    int i = blockIdx.x * 256 + threadIdx.x;
    if (i < NN) {
        float rs = g_rowsum[i];
        g_drow[i] = rs > 0.f ? rsqrtf(rs) : 0.f;
        float cs = g_colsum[i];
        g_dcol[i] = cs > 0.f ? rsqrtf(cs) : 0.f;
    }
}

__global__ void k_w1t(const float* __restrict__ W1) {
    int o = blockIdx.x * 256 + threadIdx.x;
    if (o < NH * KF) {
        int n = o / KF, k = o % KF;
        g_W1T[o] = rtf(W1[k * NH + n]);
    }
}

__global__ void k_xr(const float* __restrict__ x) {
    int i = blockIdx.x * 256 + threadIdx.x;
    if (i < NN * KF) g_xr[i] = rtf(x[i]);
}

// ---------------- tf32 GEMM: 128x128 CTA tile, 512 thr, KCH=64, ldmatrix, DEPTH=2 ----------------
// MODE 0: A=g_xr   (K=512),  B=g_W1T  -> PT, PsT(rounded)
// MODE 1: A=g_adjr (K=8192), B=g_PsT  -> Y1T, Y1sT(rounded)
// MODE 2: A=g_adjr (K=8192), B=g_Y1sT -> HT
template <int MODE>
__global__ __launch_bounds__(512) void k_tc(int K) {
    extern __shared__ float sm[];
    const float* __restrict__ A  = (MODE == 0) ? g_xr : g_adjr;
    const float* __restrict__ BT =
        (MODE == 0) ? g_W1T : (MODE == 1) ? g_PsT : g_Y1sT;

    const int tid    = threadIdx.x;
    const int lane   = tid & 31;
    const int wid    = tid >> 5;          // 0..15
    const int warp_m = wid & 3;           // 4 along M (32 rows)
    const int warp_n = wid >> 2;          // 4 along N (32 cols)
    const int row0   = blockIdx.y * 128;
    const int col0   = blockIdx.x * 128;
    const uint32_t smem0 = smem_u32(sm);

    // ---- cp.async mapping: 512 threads, per operand 128 rows x 16 granules(16B) ----
    const int crow = tid >> 2;            // 0..127
    const int cg   = tid & 3;             // granule group
    const uint32_t sA = smem0 + crow * ROWB + cg * 16;           // +i*64, + stage*STAGEB
    const uint32_t sB = sA + OPBYTES;
    const float* gA = A  + (size_t)(row0 + crow) * K + cg * 4;
    const float* gB = BT + (size_t)(col0 + crow) * K + cg * 4;

    // ---- ldmatrix addresses ----
    const int lr    = lane & 15;
    const int khalf = (lane >> 4) * 16;   // +4 floats for upper tile pair
    uint32_t aoff[2];
    #pragma unroll
    for (int mt = 0; mt < 2; mt++)
        aoff[mt] = (uint32_t)((warp_m * 32 + mt * 16 + lr) * ROWB + khalf);
    const int ln   = lane & 7;
    const int quad = lane >> 3;
    const int nrow = ((quad & 2) ? 8 : 0) + ln;
    const int kh2  = (quad & 1) ? 16 : 0;
    uint32_t boff[2];
    #pragma unroll
    for (int p = 0; p < 2; p++)
        boff[p] = (uint32_t)(OPBYTES + (warp_n * 32 + p * 16 + nrow) * ROWB + kh2);

    float acc[2][4][4];
    #pragma unroll
    for (int mt = 0; mt < 2; mt++)
        #pragma unroll
        for (int nt = 0; nt < 4; nt++)
            #pragma unroll
            for (int c = 0; c < 4; c++) acc[mt][nt][c] = 0.f;

    const int nk = K / KCH;

    // prologue: chunk 0 -> stage 0
    #pragma unroll
    for (int i = 0; i < 4; i++) {
        CP16(sA + i * 64, gA + i * 16);
        CP16(sB + i * 64, gB + i * 16);
    }
    CP_COMMIT();

    for (int kt = 0; kt < nk; kt++) {
        if (kt + 1 < nk) {
            const uint32_t so = (uint32_t)((kt + 1) & 1) * STAGEB;
            const int kg = (kt + 1) * KCH;
            #pragma unroll
            for (int i = 0; i < 4; i++) {
                CP16(sA + so + i * 64, gA + kg + i * 16);
                CP16(sB + so + i * 64, gB + kg + i * 16);
            }
        }
        CP_COMMIT();
        asm volatile("cp.async.wait_group 1;" ::: "memory");
        __syncthreads();

        const uint32_t stg = smem0 + (uint32_t)(kt & 1) * STAGEB;

        uint32_t afr[2][2][4], bfr[2][2][4];
        #pragma unroll
        for (int mt = 0; mt < 2; mt++) LDSM4(afr[0][mt], stg + aoff[mt]);
        #pragma unroll
        for (int p = 0; p < 2; p++)    LDSM4(bfr[0][p], stg + boff[p]);

        #pragma unroll
        for (int ks = 0; ks < 8; ks++) {
            const int cb = ks & 1, nb = cb ^ 1;
            if (ks < 7) {
                const uint32_t ko = (uint32_t)(ks + 1) * 32u;
                #pragma unroll
                for (int mt = 0; mt < 2; mt++) LDSM4(afr[nb][mt], stg + aoff[mt] + ko);
                #pragma unroll
                for (int p = 0; p < 2; p++)    LDSM4(bfr[nb][p], stg + boff[p] + ko);
            }
            #pragma unroll
            for (int mt = 0; mt < 2; mt++)
                #pragma unroll
                for (int nt = 0; nt < 4; nt++)
                    mma_tf32(acc[mt][nt], afr[cb][mt], &bfr[cb][nt >> 1][(nt & 1) * 2]);
        }
        __syncthreads();
    }

    // epilogue
    const int qr = lane >> 2;
    const int qc = lane & 3;
    const int r_base = row0 + warp_m * 32 + qr;
    const int c_base = col0 + warp_n * 32 + 2 * qc;
    #pragma unroll
    for (int mt = 0; mt < 2; mt++) {
        #pragma unroll
        for (int ih = 0; ih < 2; ih++) {
            const int r = r_base + mt * 16 + ih * 8;
            const float dr = g_drow[r];
            const float dc = g_dcol[r];
            #pragma unroll
            for (int nt = 0; nt < 4; nt++) {
                #pragma unroll
                for (int j = 0; j < 2; j++) {
                    const int cc = c_base + nt * 8 + j;
                    const size_t o = (size_t)cc * NN + r;
                    const float a = acc[mt][nt][2 * ih + j];
                    if (MODE == 0) {
                        g_PT[o] = a; g_PsT[o] = rtf(dc * a);
                    } else if (MODE == 1) {
                        float y = dr * a;
                        g_Y1T[o] = y; g_Y1sT[o] = rtf(dc * y);
                    } else {
                        float v = FALPHA * g_PT[o] + (FALPHA - 1.f) * g_Y1T[o] - dr * a;
                        g_HT[o] = v > 0.f ? v : 0.f;
                    }
                }
            }
        }
    }
}

// ---------------- Q = H @ W2 ----------------
__global__ __launch_bounds__(256) void k_q(const float* __restrict__ W2) {
    const int i = blockIdx.x * 256 + threadIdx.x;
    float a0 = 0.f, a1 = 0.f;
    for (int k = 0; k < NH; k++) {
        float h = g_HT[(size_t)k * NN + i];
        a0 = fmaf(h, __ldg(W2 + 2 * k + 0), a0);
        a1 = fmaf(h, __ldg(W2 + 2 * k + 1), a1);
    }
    float dcv = g_dcol[i];
    g_Q [i * 2 + 0] = a0;       g_Q [i * 2 + 1] = a1;
    g_Qs[i * 2 + 0] = dcv * a0; g_Qs[i * 2 + 1] = dcv * a1;
}

// ---------------- width-2 matvec over adj ----------------
template <int FINAL>
__global__ __launch_bounds__(256) void k_mv(const float* __restrict__ adj,
                                            const float* __restrict__ b2,
                                            float* __restrict__ out) {
    const int i    = blockIdx.x * 8 + (threadIdx.x >> 5);
    const int lane = threadIdx.x & 31;
    const float4* __restrict__ arow = reinterpret_cast<const float4*>(adj + (size_t)i * NN);
    const float2* __restrict__ S = reinterpret_cast<const float2*>(FINAL ? g_Z1s : g_Qs);
    float a0 = 0.f, a1 = 0.f;
    for (int j = lane; j < NN / 4; j += 32) {
        float4 a = arow[j];
        float2 s0 = S[4 * j + 0], s1 = S[4 * j + 1], s2 = S[4 * j + 2], s3 = S[4 * j + 3];
        a0 = fmaf(a.x, s0.x, fmaf(a.y, s1.x, fmaf(a.z, s2.x, fmaf(a.w, s3.x, a0))));
        a1 = fmaf(a.x, s0.y, fmaf(a.y, s1.y, fmaf(a.z, s2.y, fmaf(a.w, s3.y, a1))));
    }
    #pragma unroll
    for (int o = 16; o; o >>= 1) {
        a0 += __shfl_down_sync(0xffffffffu, a0, o);
        a1 += __shfl_down_sync(0xffffffffu, a1, o);
    }
    if (lane == 0) {
        const float dr = g_drow[i];
        if (!FINAL) {
            float z0 = dr * a0, z1 = dr * a1;
            float dcv = g_dcol[i];
            g_Z1 [i * 2 + 0] = z0;       g_Z1 [i * 2 + 1] = z1;
            g_Z1s[i * 2 + 0] = dcv * z0; g_Z1s[i * 2 + 1] = dcv * z1;
        } else {
            float o0 = FALPHA * g_Q[i * 2 + 0] + (FALPHA - 1.f) * g_Z1[i * 2 + 0] - dr * a0 + b2[0];
            float o1 = FALPHA * g_Q[i * 2 + 1] + (FALPHA - 1.f) * g_Z1[i * 2 + 1] - dr * a1 + b2[1];
            float m   = fmaxf(o0, o1);
            float lse = m + logf(expf(o0 - m) + expf(o1 - m));
            out[i * 2 + 0] = o0 - lse;
            out[i * 2 + 1] = o1 - lse;
        }
    }
}

extern "C" void kernel_launch(void* const* d_in, const int* in_sizes, int n_in,
                              void* d_out, int out_size) {
    const float* x   = (const float*)d_in[0];
    const float* adj = (const float*)d_in[1];
    const float* W1  = (const float*)d_in[2];
    const float* W2  = (const float*)d_in[3];
    const float* b2  = (const float*)d_in[4];
    float* out = (float*)d_out;

    cudaFuncSetAttribute(k_tc<0>, cudaFuncAttributeMaxDynamicSharedMemorySize, SM_BYTES);
    cudaFuncSetAttribute(k_tc<1>, cudaFuncAttributeMaxDynamicSharedMemorySize, SM_BYTES);
    cudaFuncSetAttribute(k_tc<2>, cudaFuncAttributeMaxDynamicSharedMemorySize, SM_BYTES);

    k_zero<<<NN / 256, 256>>>();
    dim3 gsum(8, 32);
    k_sums<<<gsum, 256>>>(adj);
    k_deg<<<NN / 256, 256>>>();
    k_w1t<<<(NH * KF) / 256, 256>>>(W1);
    k_xr<<<(NN * KF) / 256, 256>>>(x);

    dim3 gt(2, NN / 128);
    k_tc<0><<<gt, 512, SM_BYTES>>>(KF);
    k_tc<1><<<gt, 512, SM_BYTES>>>(NN);
    k_tc<2><<<gt, 512, SM_BYTES>>>(NN);

    k_q<<<NN / 256, 256>>>(W2);
    k_mv<0><<<NN / 8, 256>>>(adj, b2, out);
    k_mv<1><<<NN / 8, 256>>>(adj, b2, out);
}

// round 10
// speedup vs baseline: 1.6196x; 1.6196x over previous
#include <cuda_runtime.h>
#include <math.h>
#include <stdint.h>

#define NN 8192
#define KF 512
#define NH 256
#define FALPHA 0.5f

#define KCH 64
#define ROWB 272              // bytes per smem row: 64 floats + 16B pad (LDSM conflict-free)
#define OPBYTES (128 * ROWB)  // 34816 per operand per stage
#define STAGEB (2 * OPBYTES)  // 69632
#define SM_BYTES (2 * STAGEB) // 139264, DEPTH=2

// ---------------- device scratch ----------------
__device__ float g_rowsum[NN];
__device__ float g_colsum[NN];
__device__ float g_drow[NN];
__device__ float g_dcol[NN];
__device__ float g_W1T [NH * KF];    // W1^T rounded tf32
__device__ float g_PT  [NH * NN];    // (x@W1)^T exact
__device__ float g_PsT [NH * NN];    // (dcol ⊙ P)^T rounded tf32
__device__ float g_Y1T [NH * NN];    // (DAD@P)^T exact
__device__ float g_Y1sT[NH * NN];    // (dcol ⊙ Y1)^T rounded tf32
__device__ float g_HT  [NH * NN];    // H^T exact
__device__ float g_Q [NN * 2];
__device__ float g_Qs[NN * 2];
__device__ float g_Z1[NN * 2];
__device__ float g_Z1s[NN * 2];

// ---------------- helpers ----------------
__device__ __forceinline__ uint32_t smem_u32(const void* p) {
    uint32_t a;
    asm("{ .reg .u64 t; cvta.to.shared.u64 t, %1; cvt.u32.u64 %0, t; }" : "=r"(a) : "l"(p));
    return a;
}
__device__ __forceinline__ uint32_t f2tf(float f) {
    uint32_t r;
    asm("cvt.rna.tf32.f32 %0, %1;" : "=r"(r) : "f"(f));
    return r;
}
__device__ __forceinline__ float rtf(float f) { return __uint_as_float(f2tf(f)); }
// cheap fp32->tf32 round-to-nearest on raw bits (ALU pipe, no CVT)
__device__ __forceinline__ uint32_t rnd_tf(uint32_t u) {
    return (u + 0x1000u) & 0xFFFFE000u;
}

__device__ __forceinline__ void mma_tf32(float* d, const uint32_t* a, const uint32_t* b) {
    asm volatile(
        "mma.sync.aligned.m16n8k8.row.col.f32.tf32.tf32.f32 "
        "{%0,%1,%2,%3}, {%4,%5,%6,%7}, {%8,%9}, {%0,%1,%2,%3};"
        : "+f"(d[0]), "+f"(d[1]), "+f"(d[2]), "+f"(d[3])
        : "r"(a[0]), "r"(a[1]), "r"(a[2]), "r"(a[3]), "r"(b[0]), "r"(b[1]));
}
#define LDSM4(r, addr) \
    asm volatile("ldmatrix.sync.aligned.m8n8.x4.shared.b16 {%0,%1,%2,%3}, [%4];" \
        : "=r"((r)[0]), "=r"((r)[1]), "=r"((r)[2]), "=r"((r)[3]) : "r"(addr))
#define CP16(dst, src) \
    asm volatile("cp.async.cg.shared.global [%0], [%1], 16;" :: "r"(dst), "l"(src) : "memory")
#define CP_COMMIT() asm volatile("cp.async.commit_group;" ::: "memory")

// ---------------- small kernels ----------------
__global__ void k_zero() {
    int i = blockIdx.x * 256 + threadIdx.x;
    if (i < NN) { g_rowsum[i] = 0.f; g_colsum[i] = 0.f; }
}

// row/col sums over exact adj (read-only pass)
__global__ __launch_bounds__(256) void k_sums(const float* __restrict__ adj) {
    const int t    = threadIdx.x;
    const int c0   = blockIdx.x * 1024 + t * 4;
    const int r0   = blockIdx.y * 256;
    const int lane = t & 31;
    float4 cacc = make_float4(0.f, 0.f, 0.f, 0.f);
    for (int r = 0; r < 256; r++) {
        float4 v = *reinterpret_cast<const float4*>(adj + (size_t)(r0 + r) * NN + c0);
        cacc.x += v.x; cacc.y += v.y; cacc.z += v.z; cacc.w += v.w;
        float rs = (v.x + v.y) + (v.z + v.w);
        #pragma unroll
        for (int o = 16; o; o >>= 1) rs += __shfl_down_sync(0xffffffffu, rs, o);
        if (lane == 0) atomicAdd(&g_rowsum[r0 + r], rs);
    }
    atomicAdd(&g_colsum[c0 + 0], cacc.x);
    atomicAdd(&g_colsum[c0 + 1], cacc.y);
    atomicAdd(&g_colsum[c0 + 2], cacc.z);
    atomicAdd(&g_colsum[c0 + 3], cacc.w);
}

__global__ void k_deg() {
    int i = blockIdx.x * 256 + threadIdx.x;
    if (i < NN) {
        float rs = g_rowsum[i];
        g_drow[i] = rs > 0.f ? rsqrtf(rs) : 0.f;
        float cs = g_colsum[i];
        g_dcol[i] = cs > 0.f ? rsqrtf(cs) : 0.f;
    }
}

__global__ void k_w1t(const float* __restrict__ W1) {
    int o = blockIdx.x * 256 + threadIdx.x;
    if (o < NH * KF) {
        int n = o / KF, k = o % KF;
        g_W1T[o] = rtf(W1[k * NH + n]);
    }
}

// ---------------- tf32 GEMM: 128x128 CTA tile, 512 thr, KCH=64, ldmatrix, DEPTH=2 ----------------
// A is RAW fp32 (x or adj), rounded to tf32 in registers after ldmatrix.
// B is pre-rounded tf32 (g_W1T / g_PsT / g_Y1sT).
// MODE 0: A=x   (K=512)  -> PT, PsT(rounded)
// MODE 1: A=adj (K=8192) -> Y1T = drow*acc, Y1sT(rounded)
// MODE 2: A=adj (K=8192) -> HT = relu(a*PT + (a-1)*Y1T - drow*acc)
template <int MODE>
__global__ __launch_bounds__(512) void k_tc(const float* __restrict__ A, int K) {
    extern __shared__ float sm[];
    const float* __restrict__ BT =
        (MODE == 0) ? g_W1T : (MODE == 1) ? g_PsT : g_Y1sT;

    const int tid    = threadIdx.x;
    const int lane   = tid & 31;
    const int wid    = tid >> 5;          // 0..15
    const int warp_m = wid & 3;           // 4 along M (32 rows)
    const int warp_n = wid >> 2;          // 4 along N (32 cols)
    const int row0   = blockIdx.y * 128;
    const int col0   = blockIdx.x * 128;
    const uint32_t smem0 = smem_u32(sm);

    // cp.async mapping: 512 threads, per operand 128 rows x 4 granule-groups(16B)
    const int crow = tid >> 2;            // 0..127
    const int cg   = tid & 3;
    const uint32_t sA = smem0 + crow * ROWB + cg * 16;
    const uint32_t sB = sA + OPBYTES;
    const float* gA = A  + (size_t)(row0 + crow) * K + cg * 4;
    const float* gB = BT + (size_t)(col0 + crow) * K + cg * 4;

    // ldmatrix addresses
    const int lr    = lane & 15;
    const int khalf = (lane >> 4) * 16;
    uint32_t aoff[2];
    #pragma unroll
    for (int mt = 0; mt < 2; mt++)
        aoff[mt] = (uint32_t)((warp_m * 32 + mt * 16 + lr) * ROWB + khalf);
    const int ln   = lane & 7;
    const int quad = lane >> 3;
    const int nrow = ((quad & 2) ? 8 : 0) + ln;
    const int kh2  = (quad & 1) ? 16 : 0;
    uint32_t boff[2];
    #pragma unroll
    for (int p = 0; p < 2; p++)
        boff[p] = (uint32_t)(OPBYTES + (warp_n * 32 + p * 16 + nrow) * ROWB + kh2);

    float acc[2][4][4];
    #pragma unroll
    for (int mt = 0; mt < 2; mt++)
        #pragma unroll
        for (int nt = 0; nt < 4; nt++)
            #pragma unroll
            for (int c = 0; c < 4; c++) acc[mt][nt][c] = 0.f;

    const int nk = K / KCH;

    // prologue: chunk 0 -> stage 0
    #pragma unroll
    for (int i = 0; i < 4; i++) {
        CP16(sA + i * 64, gA + i * 16);
        CP16(sB + i * 64, gB + i * 16);
    }
    CP_COMMIT();

    for (int kt = 0; kt < nk; kt++) {
        if (kt + 1 < nk) {
            const uint32_t so = (uint32_t)((kt + 1) & 1) * STAGEB;
            const int kg = (kt + 1) * KCH;
            #pragma unroll
            for (int i = 0; i < 4; i++) {
                CP16(sA + so + i * 64, gA + kg + i * 16);
                CP16(sB + so + i * 64, gB + kg + i * 16);
            }
        }
        CP_COMMIT();
        asm volatile("cp.async.wait_group 1;" ::: "memory");
        __syncthreads();

        const uint32_t stg = smem0 + (uint32_t)(kt & 1) * STAGEB;

        uint32_t afr[2][2][4], bfr[2][2][4];
        #pragma unroll
        for (int mt = 0; mt < 2; mt++) {
            LDSM4(afr[0][mt], stg + aoff[mt]);
            #pragma unroll
            for (int r = 0; r < 4; r++) afr[0][mt][r] = rnd_tf(afr[0][mt][r]);
        }
        #pragma unroll
        for (int p = 0; p < 2; p++) LDSM4(bfr[0][p], stg + boff[p]);

        #pragma unroll
        for (int ks = 0; ks < 8; ks++) {
            const int cb = ks & 1, nb = cb ^ 1;
            if (ks < 7) {
                const uint32_t ko = (uint32_t)(ks + 1) * 32u;
                #pragma unroll
                for (int mt = 0; mt < 2; mt++) {
                    LDSM4(afr[nb][mt], stg + aoff[mt] + ko);
                    #pragma unroll
                    for (int r = 0; r < 4; r++) afr[nb][mt][r] = rnd_tf(afr[nb][mt][r]);
                }
                #pragma unroll
                for (int p = 0; p < 2; p++) LDSM4(bfr[nb][p], stg + boff[p] + ko);
            }
            #pragma unroll
            for (int mt = 0; mt < 2; mt++)
                #pragma unroll
                for (int nt = 0; nt < 4; nt++)
                    mma_tf32(acc[mt][nt], afr[cb][mt], &bfr[cb][nt >> 1][(nt & 1) * 2]);
        }
        __syncthreads();
    }

    // epilogue
    const int qr = lane >> 2;
    const int qc = lane & 3;
    const int r_base = row0 + warp_m * 32 + qr;
    const int c_base = col0 + warp_n * 32 + 2 * qc;
    #pragma unroll
    for (int mt = 0; mt < 2; mt++) {
        #pragma unroll
        for (int ih = 0; ih < 2; ih++) {
            const int r = r_base + mt * 16 + ih * 8;
            const float dr = g_drow[r];
            const float dc = g_dcol[r];
            #pragma unroll
            for (int nt = 0; nt < 4; nt++) {
                #pragma unroll
                for (int j = 0; j < 2; j++) {
                    const int cc = c_base + nt * 8 + j;
                    const size_t o = (size_t)cc * NN + r;
                    const float a = acc[mt][nt][2 * ih + j];
                    if (MODE == 0) {
                        g_PT[o] = a; g_PsT[o] = rtf(dc * a);
                    } else if (MODE == 1) {
                        float y = dr * a;
                        g_Y1T[o] = y; g_Y1sT[o] = rtf(dc * y);
                    } else {
                        float v = FALPHA * g_PT[o] + (FALPHA - 1.f) * g_Y1T[o] - dr * a;
                        g_HT[o] = v > 0.f ? v : 0.f;
                    }
                }
            }
        }
    }
}

// ---------------- Q = H @ W2 ----------------
__global__ __launch_bounds__(256) void k_q(const float* __restrict__ W2) {
    const int i = blockIdx.x * 256 + threadIdx.x;
    float a0 = 0.f, a1 = 0.f;
    for (int k = 0; k < NH; k++) {
        float h = g_HT[(size_t)k * NN + i];
        a0 = fmaf(h, __ldg(W2 + 2 * k + 0), a0);
        a1 = fmaf(h, __ldg(W2 + 2 * k + 1), a1);
    }
    float dcv = g_dcol[i];
    g_Q [i * 2 + 0] = a0;       g_Q [i * 2 + 1] = a1;
    g_Qs[i * 2 + 0] = dcv * a0; g_Qs[i * 2 + 1] = dcv * a1;
}

// ---------------- width-2 matvec over adj ----------------
template <int FINAL>
__global__ __launch_bounds__(256) void k_mv(const float* __restrict__ adj,
                                            const float* __restrict__ b2,
                                            float* __restrict__ out) {
    const int i    = blockIdx.x * 8 + (threadIdx.x >> 5);
    const int lane = threadIdx.x & 31;
    const float4* __restrict__ arow = reinterpret_cast<const float4*>(adj + (size_t)i * NN);
    const float2* __restrict__ S = reinterpret_cast<const float2*>(FINAL ? g_Z1s : g_Qs);
    float a0 = 0.f, a1 = 0.f;
    for (int j = lane; j < NN / 4; j += 32) {
        float4 a = arow[j];
        float2 s0 = S[4 * j + 0], s1 = S[4 * j + 1], s2 = S[4 * j + 2], s3 = S[4 * j + 3];
        a0 = fmaf(a.x, s0.x, fmaf(a.y, s1.x, fmaf(a.z, s2.x, fmaf(a.w, s3.x, a0))));
        a1 = fmaf(a.x, s0.y, fmaf(a.y, s1.y, fmaf(a.z, s2.y, fmaf(a.w, s3.y, a1))));
    }
    #pragma unroll
    for (int o = 16; o; o >>= 1) {
        a0 += __shfl_down_sync(0xffffffffu, a0, o);
        a1 += __shfl_down_sync(0xffffffffu, a1, o);
    }
    if (lane == 0) {
        const float dr = g_drow[i];
        if (!FINAL) {
            float z0 = dr * a0, z1 = dr * a1;
            float dcv = g_dcol[i];
            g_Z1 [i * 2 + 0] = z0;       g_Z1 [i * 2 + 1] = z1;
            g_Z1s[i * 2 + 0] = dcv * z0; g_Z1s[i * 2 + 1] = dcv * z1;
        } else {
            float o0 = FALPHA * g_Q[i * 2 + 0] + (FALPHA - 1.f) * g_Z1[i * 2 + 0] - dr * a0 + b2[0];
            float o1 = FALPHA * g_Q[i * 2 + 1] + (FALPHA - 1.f) * g_Z1[i * 2 + 1] - dr * a1 + b2[1];
            float m   = fmaxf(o0, o1);
            float lse = m + logf(expf(o0 - m) + expf(o1 - m));
            out[i * 2 + 0] = o0 - lse;
            out[i * 2 + 1] = o1 - lse;
        }
    }
}

extern "C" void kernel_launch(void* const* d_in, const int* in_sizes, int n_in,
                              void* d_out, int out_size) {
    const float* x   = (const float*)d_in[0];
    const float* adj = (const float*)d_in[1];
    const float* W1  = (const float*)d_in[2];
    const float* W2  = (const float*)d_in[3];
    const float* b2  = (const float*)d_in[4];
    float* out = (float*)d_out;

    cudaFuncSetAttribute(k_tc<0>, cudaFuncAttributeMaxDynamicSharedMemorySize, SM_BYTES);
    cudaFuncSetAttribute(k_tc<1>, cudaFuncAttributeMaxDynamicSharedMemorySize, SM_BYTES);
    cudaFuncSetAttribute(k_tc<2>, cudaFuncAttributeMaxDynamicSharedMemorySize, SM_BYTES);

    // launch order chosen so the big adj-GEMM k_tc<1> sits at index 5 for ncu
    k_zero<<<NN / 256, 256>>>();                       // 0
    dim3 gsum(8, 32);
    k_sums<<<gsum, 256>>>(adj);                        // 1
    k_deg<<<NN / 256, 256>>>();                        // 2
    k_w1t<<<(NH * KF) / 256, 256>>>(W1);               // 3

    dim3 gt(2, NN / 128);
    k_tc<0><<<gt, 512, SM_BYTES>>>(x, KF);             // 4
    k_tc<1><<<gt, 512, SM_BYTES>>>(adj, NN);           // 5  <- ncu target
    k_tc<2><<<gt, 512, SM_BYTES>>>(adj, NN);           // 6

    k_q<<<NN / 256, 256>>>(W2);                        // 7
    k_mv<0><<<NN / 8, 256>>>(adj, b2, out);            // 8
    k_mv<1><<<NN / 8, 256>>>(adj, b2, out);            // 9
}

// round 11
// speedup vs baseline: 1.6400x; 1.0126x over previous
#include <cuda_runtime.h>
#include <math.h>
#include <stdint.h>

#define NN 8192
#define KF 512
#define NH 256
#define FALPHA 0.5f

#define KCH 64
#define ROWB 272              // bytes per smem row: 64 floats + 16B pad (LDSM conflict-free)
#define OPBYTES (128 * ROWB)  // 34816 per operand per stage
#define STAGEB (2 * OPBYTES)  // 69632
#define DEPTH 3
#define SM_BYTES (DEPTH * STAGEB) // 208896

// ---------------- device scratch ----------------
__device__ float g_rowsum[NN];
__device__ float g_colsum[NN];
__device__ float g_drow[NN];
__device__ float g_dcol[NN];
__device__ float g_W1T [NH * KF];    // W1^T rounded tf32
__device__ float g_PT  [NH * NN];    // (x@W1)^T exact
__device__ float g_PsT [NH * NN];    // (dcol ⊙ P)^T rounded tf32
__device__ float g_Y1T [NH * NN];    // (DAD@P)^T exact
__device__ float g_Y1sT[NH * NN];    // (dcol ⊙ Y1)^T rounded tf32
__device__ float g_HT  [NH * NN];    // H^T exact
__device__ float g_Q [NN * 2];
__device__ float g_Qs[NN * 2];
__device__ float g_Z1[NN * 2];
__device__ float g_Z1s[NN * 2];

// ---------------- helpers ----------------
__device__ __forceinline__ uint32_t smem_u32(const void* p) {
    uint32_t a;
    asm("{ .reg .u64 t; cvta.to.shared.u64 t, %1; cvt.u32.u64 %0, t; }" : "=r"(a) : "l"(p));
    return a;
}
__device__ __forceinline__ uint32_t f2tf(float f) {
    uint32_t r;
    asm("cvt.rna.tf32.f32 %0, %1;" : "=r"(r) : "f"(f));
    return r;
}
__device__ __forceinline__ float rtf(float f) { return __uint_as_float(f2tf(f)); }
// cheap fp32->tf32 round-to-nearest on raw bits (ALU pipe, no CVT)
__device__ __forceinline__ uint32_t rnd_tf(uint32_t u) {
    return (u + 0x1000u) & 0xFFFFE000u;
}

__device__ __forceinline__ void mma_tf32(float* d, const uint32_t* a, const uint32_t* b) {
    asm volatile(
        "mma.sync.aligned.m16n8k8.row.col.f32.tf32.tf32.f32 "
        "{%0,%1,%2,%3}, {%4,%5,%6,%7}, {%8,%9}, {%0,%1,%2,%3};"
        : "+f"(d[0]), "+f"(d[1]), "+f"(d[2]), "+f"(d[3])
        : "r"(a[0]), "r"(a[1]), "r"(a[2]), "r"(a[3]), "r"(b[0]), "r"(b[1]));
}
#define LDSM4(r, addr) \
    asm volatile("ldmatrix.sync.aligned.m8n8.x4.shared.b16 {%0,%1,%2,%3}, [%4];" \
        : "=r"((r)[0]), "=r"((r)[1]), "=r"((r)[2]), "=r"((r)[3]) : "r"(addr))
#define CP16(dst, src) \
    asm volatile("cp.async.cg.shared.global [%0], [%1], 16;" :: "r"(dst), "l"(src) : "memory")
#define CP_COMMIT() asm volatile("cp.async.commit_group;" ::: "memory")

// ---------------- small kernels ----------------
__global__ void k_zero() {
    int i = blockIdx.x * 256 + threadIdx.x;
    if (i < NN) { g_rowsum[i] = 0.f; g_colsum[i] = 0.f; }
}

// row/col sums over exact adj (read-only pass)
__global__ __launch_bounds__(256) void k_sums(const float* __restrict__ adj) {
    const int t    = threadIdx.x;
    const int c0   = blockIdx.x * 1024 + t * 4;
    const int r0   = blockIdx.y * 256;
    const int lane = t & 31;
    float4 cacc = make_float4(0.f, 0.f, 0.f, 0.f);
    for (int r = 0; r < 256; r++) {
        float4 v = *reinterpret_cast<const float4*>(adj + (size_t)(r0 + r) * NN + c0);
        cacc.x += v.x; cacc.y += v.y; cacc.z += v.z; cacc.w += v.w;
        float rs = (v.x + v.y) + (v.z + v.w);
        #pragma unroll
        for (int o = 16; o; o >>= 1) rs += __shfl_down_sync(0xffffffffu, rs, o);
        if (lane == 0) atomicAdd(&g_rowsum[r0 + r], rs);
    }
    atomicAdd(&g_colsum[c0 + 0], cacc.x);
    atomicAdd(&g_colsum[c0 + 1], cacc.y);
    atomicAdd(&g_colsum[c0 + 2], cacc.z);
    atomicAdd(&g_colsum[c0 + 3], cacc.w);
}

__global__ void k_deg() {
    int i = blockIdx.x * 256 + threadIdx.x;
    if (i < NN) {
        float rs = g_rowsum[i];
        g_drow[i] = rs > 0.f ? rsqrtf(rs) : 0.f;
        float cs = g_colsum[i];
        g_dcol[i] = cs > 0.f ? rsqrtf(cs) : 0.f;
    }
}

__global__ void k_w1t(const float* __restrict__ W1) {
    int o = blockIdx.x * 256 + threadIdx.x;
    if (o < NH * KF) {
        int n = o / KF, k = o % KF;
        g_W1T[o] = rtf(W1[k * NH + n]);
    }
}

// ---------------- tf32 GEMM: 128x128 CTA tile, 512 thr ----------------
// 8 cells (2M x 4N, 64x32 each) x 2-way K-split = 16 warps. DEPTH=3, 1 sync/chunk.
// A RAW fp32 (rounded to tf32 in regs); B pre-rounded tf32.
// MODE 0: A=x   (K=512)  -> PT, PsT(rounded)
// MODE 1: A=adj (K=8192) -> Y1T = drow*acc, Y1sT(rounded)
// MODE 2: A=adj (K=8192) -> HT = relu(a*PT + (a-1)*Y1T - drow*acc)
template <int MODE>
__global__ __launch_bounds__(512) void k_tc(const float* __restrict__ A, int K) {
    extern __shared__ float sm[];
    const float* __restrict__ BT =
        (MODE == 0) ? g_W1T : (MODE == 1) ? g_PsT : g_Y1sT;

    const int tid    = threadIdx.x;
    const int lane   = tid & 31;
    const int wid    = tid >> 5;          // 0..15
    const int cell   = wid & 7;           // 8 cells
    const int kh     = wid >> 3;          // k-half of chunk (0/1)
    const int cell_m = cell & 1;          // 2 groups of 64 rows
    const int cell_n = cell >> 1;         // 4 groups of 32 cols
    const int row0   = blockIdx.y * 128;
    const int col0   = blockIdx.x * 128;
    const uint32_t smem0 = smem_u32(sm);

    // cp.async mapping: 512 threads, per operand 128 rows x 4 granule-groups(16B)
    const int crow = tid >> 2;            // 0..127
    const int cg   = tid & 3;
    const uint32_t sA = smem0 + crow * ROWB + cg * 16;
    const uint32_t sB = sA + OPBYTES;
    const float* gA = A  + (size_t)(row0 + crow) * K + cg * 4;
    const float* gB = BT + (size_t)(col0 + crow) * K + cg * 4;

    // ldmatrix addresses (per-warp k-half baked in via kh*128 bytes = 32 floats)
    const int lr    = lane & 15;
    const int ahalf = (lane >> 4) * 16;
    uint32_t aoff[4];
    #pragma unroll
    for (int mt = 0; mt < 4; mt++)
        aoff[mt] = (uint32_t)((cell_m * 64 + mt * 16 + lr) * ROWB + ahalf + kh * 128);
    const int ln   = lane & 7;
    const int quad = lane >> 3;
    const int nrow = ((quad & 2) ? 8 : 0) + ln;
    const int kh2  = (quad & 1) ? 16 : 0;
    uint32_t boff[2];
    #pragma unroll
    for (int p = 0; p < 2; p++)
        boff[p] = (uint32_t)(OPBYTES + (cell_n * 32 + p * 16 + nrow) * ROWB + kh2 + kh * 128);

    float acc[4][4][4];
    #pragma unroll
    for (int mt = 0; mt < 4; mt++)
        #pragma unroll
        for (int nt = 0; nt < 4; nt++)
            #pragma unroll
            for (int c = 0; c < 4; c++) acc[mt][nt][c] = 0.f;

    const int nk = K / KCH;

    // prologue: chunks 0 and 1
    #pragma unroll
    for (int s = 0; s < 2; s++) {
        const uint32_t so = (uint32_t)s * STAGEB;
        const int kg = s * KCH;
        #pragma unroll
        for (int i = 0; i < 4; i++) {
            CP16(sA + so + i * 64, gA + kg + i * 16);
            CP16(sB + so + i * 64, gB + kg + i * 16);
        }
        CP_COMMIT();
    }

    for (int kt = 0; kt < nk; kt++) {
        asm volatile("cp.async.wait_group 1;" ::: "memory");
        __syncthreads();

        // prefetch chunk kt+2 (stage last read at chunk kt-1; barrier above makes it safe)
        if (kt + 2 < nk) {
            const uint32_t so = (uint32_t)((kt + 2) % DEPTH) * STAGEB;
            const int kg = (kt + 2) * KCH;
            #pragma unroll
            for (int i = 0; i < 4; i++) {
                CP16(sA + so + i * 64, gA + kg + i * 16);
                CP16(sB + so + i * 64, gB + kg + i * 16);
            }
        }
        CP_COMMIT();

        const uint32_t stg = smem0 + (uint32_t)(kt % DEPTH) * STAGEB;

        // B double-buffered across the 4 k-steps of this warp's k-half
        uint32_t bfr[2][2][4];
        #pragma unroll
        for (int p = 0; p < 2; p++) LDSM4(bfr[0][p], stg + boff[p]);

        #pragma unroll
        for (int ks = 0; ks < 4; ks++) {
            const int cb = ks & 1, nb = cb ^ 1;
            if (ks < 3) {
                const uint32_t ko = (uint32_t)(ks + 1) * 32u;
                #pragma unroll
                for (int p = 0; p < 2; p++) LDSM4(bfr[nb][p], stg + boff[p] + ko);
            }
            uint32_t afr[4][4];
            #pragma unroll
            for (int mt = 0; mt < 4; mt++) {
                LDSM4(afr[mt], stg + aoff[mt] + (uint32_t)ks * 32u);
                #pragma unroll
                for (int r = 0; r < 4; r++) afr[mt][r] = rnd_tf(afr[mt][r]);
            }
            #pragma unroll
            for (int mt = 0; mt < 4; mt++)
                #pragma unroll
                for (int nt = 0; nt < 4; nt++)
                    mma_tf32(acc[mt][nt], afr[mt], &bfr[cb][nt >> 1][(nt & 1) * 2]);
        }
    }

    // ---- combine K-split partials via smem scratch (stride 65 floats: conflict-free) ----
    asm volatile("cp.async.wait_group 0;" ::: "memory");
    __syncthreads();
    if (kh == 1) {
        float* dst = sm + (cell * 32 + lane) * 65;
        #pragma unroll
        for (int mt = 0; mt < 4; mt++)
            #pragma unroll
            for (int nt = 0; nt < 4; nt++)
                #pragma unroll
                for (int c = 0; c < 4; c++)
                    dst[mt * 16 + nt * 4 + c] = acc[mt][nt][c];
    }
    __syncthreads();
    if (kh == 0) {
        const float* src = sm + (cell * 32 + lane) * 65;
        #pragma unroll
        for (int mt = 0; mt < 4; mt++)
            #pragma unroll
            for (int nt = 0; nt < 4; nt++)
                #pragma unroll
                for (int c = 0; c < 4; c++)
                    acc[mt][nt][c] += src[mt * 16 + nt * 4 + c];

        // epilogue (lower warps only; each covers its 64x32 cell)
        const int qr = lane >> 2;
        const int qc = lane & 3;
        const int r_base = row0 + cell_m * 64 + qr;
        const int c_base = col0 + cell_n * 32 + 2 * qc;
        #pragma unroll
        for (int mt = 0; mt < 4; mt++) {
            #pragma unroll
            for (int ih = 0; ih < 2; ih++) {
                const int r = r_base + mt * 16 + ih * 8;
                const float dr = g_drow[r];
                const float dc = g_dcol[r];
                #pragma unroll
                for (int nt = 0; nt < 4; nt++) {
                    #pragma unroll
                    for (int j = 0; j < 2; j++) {
                        const int cc = c_base + nt * 8 + j;
                        const size_t o = (size_t)cc * NN + r;
                        const float a = acc[mt][nt][2 * ih + j];
                        if (MODE == 0) {
                            g_PT[o] = a; g_PsT[o] = rtf(dc * a);
                        } else if (MODE == 1) {
                            float y = dr * a;
                            g_Y1T[o] = y; g_Y1sT[o] = rtf(dc * y);
                        } else {
                            float v = FALPHA * g_PT[o] + (FALPHA - 1.f) * g_Y1T[o] - dr * a;
                            g_HT[o] = v > 0.f ? v : 0.f;
                        }
                    }
                }
            }
        }
    }
}

// ---------------- Q = H @ W2 ----------------
__global__ __launch_bounds__(256) void k_q(const float* __restrict__ W2) {
    const int i = blockIdx.x * 256 + threadIdx.x;
    float a0 = 0.f, a1 = 0.f;
    for (int k = 0; k < NH; k++) {
        float h = g_HT[(size_t)k * NN + i];
        a0 = fmaf(h, __ldg(W2 + 2 * k + 0), a0);
        a1 = fmaf(h, __ldg(W2 + 2 * k + 1), a1);
    }
    float dcv = g_dcol[i];
    g_Q [i * 2 + 0] = a0;       g_Q [i * 2 + 1] = a1;
    g_Qs[i * 2 + 0] = dcv * a0; g_Qs[i * 2 + 1] = dcv * a1;
}

// ---------------- width-2 matvec over adj ----------------
template <int FINAL>
__global__ __launch_bounds__(256) void k_mv(const float* __restrict__ adj,
                                            const float* __restrict__ b2,
                                            float* __restrict__ out) {
    const int i    = blockIdx.x * 8 + (threadIdx.x >> 5);
    const int lane = threadIdx.x & 31;
    const float4* __restrict__ arow = reinterpret_cast<const float4*>(adj + (size_t)i * NN);
    const float2* __restrict__ S = reinterpret_cast<const float2*>(FINAL ? g_Z1s : g_Qs);
    float a0 = 0.f, a1 = 0.f;
    for (int j = lane; j < NN / 4; j += 32) {
        float4 a = arow[j];
        float2 s0 = S[4 * j + 0], s1 = S[4 * j + 1], s2 = S[4 * j + 2], s3 = S[4 * j + 3];
        a0 = fmaf(a.x, s0.x, fmaf(a.y, s1.x, fmaf(a.z, s2.x, fmaf(a.w, s3.x, a0))));
        a1 = fmaf(a.x, s0.y, fmaf(a.y, s1.y, fmaf(a.z, s2.y, fmaf(a.w, s3.y, a1))));
    }
    #pragma unroll
    for (int o = 16; o; o >>= 1) {
        a0 += __shfl_down_sync(0xffffffffu, a0, o);
        a1 += __shfl_down_sync(0xffffffffu, a1, o);
    }
    if (lane == 0) {
        const float dr = g_drow[i];
        if (!FINAL) {
            float z0 = dr * a0, z1 = dr * a1;
            float dcv = g_dcol[i];
            g_Z1 [i * 2 + 0] = z0;       g_Z1 [i * 2 + 1] = z1;
            g_Z1s[i * 2 + 0] = dcv * z0; g_Z1s[i * 2 + 1] = dcv * z1;
        } else {
            float o0 = FALPHA * g_Q[i * 2 + 0] + (FALPHA - 1.f) * g_Z1[i * 2 + 0] - dr * a0 + b2[0];
            float o1 = FALPHA * g_Q[i * 2 + 1] + (FALPHA - 1.f) * g_Z1[i * 2 + 1] - dr * a1 + b2[1];
            float m   = fmaxf(o0, o1);
            float lse = m + logf(expf(o0 - m) + expf(o1 - m));
            out[i * 2 + 0] = o0 - lse;
            out[i * 2 + 1] = o1 - lse;
        }
    }
}

extern "C" void kernel_launch(void* const* d_in, const int* in_sizes, int n_in,
                              void* d_out, int out_size) {
    const float* x   = (const float*)d_in[0];
    const float* adj = (const float*)d_in[1];
    const float* W1  = (const float*)d_in[2];
    const float* W2  = (const float*)d_in[3];
    const float* b2  = (const float*)d_in[4];
    float* out = (float*)d_out;

    cudaFuncSetAttribute(k_tc<0>, cudaFuncAttributeMaxDynamicSharedMemorySize, SM_BYTES);
    cudaFuncSetAttribute(k_tc<1>, cudaFuncAttributeMaxDynamicSharedMemorySize, SM_BYTES);
    cudaFuncSetAttribute(k_tc<2>, cudaFuncAttributeMaxDynamicSharedMemorySize, SM_BYTES);

    k_zero<<<NN / 256, 256>>>();                       // 0
    dim3 gsum(8, 32);
    k_sums<<<gsum, 256>>>(adj);                        // 1
    k_deg<<<NN / 256, 256>>>();                        // 2
    k_w1t<<<(NH * KF) / 256, 256>>>(W1);               // 3

    dim3 gt(2, NN / 128);
    k_tc<0><<<gt, 512, SM_BYTES>>>(x, KF);             // 4
    k_tc<1><<<gt, 512, SM_BYTES>>>(adj, NN);           // 5  <- ncu target
    k_tc<2><<<gt, 512, SM_BYTES>>>(adj, NN);           // 6

    k_q<<<NN / 256, 256>>>(W2);                        // 7
    k_mv<0><<<NN / 8, 256>>>(adj, b2, out);            // 8
    k_mv<1><<<NN / 8, 256>>>(adj, b2, out);            // 9
}